// round 6
// baseline (speedup 1.0000x reference)
#include <cuda_runtime.h>
#include <math_constants.h>

#define HW 9216            // 96*96
#define CK 392             // 256 + 136
#define NF (256 * HW)      // visual-feature element count
#define NTOT (CK * HW)     // concat element count = 3612672
#define NCHUNK 32
#define ROWS_PER_CHUNK (HW / NCHUNK)   // 288

// ---- static device scratch (no dynamic allocation allowed) ----
__device__ __align__(16) float g_SRC[NTOT];                 // (9216, 392) row-major
__device__ __align__(16) float g_REF[NTOT];                 // (392, 9216) row-major
__device__ __align__(16) float g_A[(size_t)HW * HW];        // 340 MB logits
__device__ float g_pm[NCHUNK * HW];
__device__ float g_ps[NCHUNK * HW];
__device__ float g_beta[HW], g_gama[HW], g_M[HW];
__device__ float g_colmax[HW], g_wb[HW], g_wg[HW];
__device__ float g_bhat[HW], g_ghat[HW];

// 1) Build the flattened concat buffers. The torch/jax "raw reshape" of the
//    channel-concat is exactly the contiguous flat buffer, so SRC/REF become
//    plain row-major GEMM operands.
__global__ void prep_concat(const float* __restrict__ fs, const float* __restrict__ fr,
                            const float* __restrict__ ls, const float* __restrict__ lr) {
    int t = blockIdx.x * blockDim.x + threadIdx.x;
    if (t >= NTOT) return;
    if (t < NF) {
        g_SRC[t] = 0.01f * fs[t];
        g_REF[t] = 0.01f * fr[t];
    } else {
        g_SRC[t] = ls[t - NF];
        g_REF[t] = lr[t - NF];
    }
}

// 2) 1x1 convs (256->1) + mask equality vector.
__global__ void prep_betagama(const float* __restrict__ fr,
                              const int* __restrict__ ms, const int* __restrict__ mr,
                              const float* __restrict__ w1, const float* __restrict__ b1,
                              const float* __restrict__ w2, const float* __restrict__ b2) {
    int p = blockIdx.x * blockDim.x + threadIdx.x;
    if (p >= HW) return;
    float b = b1[0], g = b2[0];
#pragma unroll 8
    for (int c = 0; c < 256; c++) {
        float v = fr[c * HW + p];          // coalesced across p
        b = fmaf(v, w1[c], b);
        g = fmaf(v, w2[c], g);
    }
    g_beta[p] = b;
    g_gama[p] = g;
    g_M[p] = (ms[p] == mr[p]) ? 1.0f : 0.0f;
}

// 3) fp32 SGEMM: g_A = g_SRC (9216x392) @ g_REF (392x9216).
//    128x128 block tile, BK=8, 256 threads, 8x8 per thread (split 4+4 to keep
//    LDS.128 conflict-free). K=392 = 49*8, M=N divisible by 128: no bounds checks.
__global__ void __launch_bounds__(256) sgemm_kernel() {
    __shared__ __align__(16) float As[8][128];
    __shared__ __align__(16) float Bs[8][128];
    const int tid = threadIdx.x;
    const int tx = tid & 15;        // 0..15  -> N direction
    const int ty = tid >> 4;        // 0..15  -> M direction
    const float* Ab = g_SRC + (size_t)blockIdx.y * 128 * CK;
    const float* Bb = g_REF + (size_t)blockIdx.x * 128;

    const int arow = tid >> 1, acol = (tid & 1) * 4;   // A: 128 rows x 8 k, float4/thread
    const int brow = tid >> 5, bcol = (tid & 31) * 4;  // B: 8 k x 128 cols, float4/thread

    float acc[8][8];
#pragma unroll
    for (int i = 0; i < 8; i++)
#pragma unroll
        for (int j = 0; j < 8; j++) acc[i][j] = 0.0f;

    for (int k0 = 0; k0 < CK; k0 += 8) {
        float4 av = *(const float4*)(Ab + (size_t)arow * CK + k0 + acol);
        float4 bv = *(const float4*)(Bb + (size_t)(k0 + brow) * HW + bcol);
        __syncthreads();
        As[acol + 0][arow] = av.x;
        As[acol + 1][arow] = av.y;
        As[acol + 2][arow] = av.z;
        As[acol + 3][arow] = av.w;
        *(float4*)&Bs[brow][bcol] = bv;
        __syncthreads();
#pragma unroll
        for (int k = 0; k < 8; k++) {
            float4 a0 = *(const float4*)&As[k][ty * 4];
            float4 a1 = *(const float4*)&As[k][ty * 4 + 64];
            float4 b0 = *(const float4*)&Bs[k][tx * 4];
            float4 b1 = *(const float4*)&Bs[k][tx * 4 + 64];
            float ar[8] = {a0.x, a0.y, a0.z, a0.w, a1.x, a1.y, a1.z, a1.w};
            float br[8] = {b0.x, b0.y, b0.z, b0.w, b1.x, b1.y, b1.z, b1.w};
#pragma unroll
            for (int i = 0; i < 8; i++)
#pragma unroll
                for (int j = 0; j < 8; j++) acc[i][j] = fmaf(ar[i], br[j], acc[i][j]);
        }
    }

    const size_t crow0 = (size_t)blockIdx.y * 128 + ty * 4;
    const size_t ccol0 = (size_t)blockIdx.x * 128 + tx * 4;
#pragma unroll
    for (int i = 0; i < 8; i++) {
        size_t r = crow0 + (i & 3) + (i >> 2) * 64;
        float* Cp = g_A + r * HW + ccol0;
        *(float4*)Cp        = make_float4(acc[i][0], acc[i][1], acc[i][2], acc[i][3]);
        *(float4*)(Cp + 64) = make_float4(acc[i][4], acc[i][5], acc[i][6], acc[i][7]);
    }
}

// 4) Per-column online (max, sum-exp) over a 288-row chunk. Thread = one column,
//    consecutive threads = consecutive columns -> fully coalesced A reads.
__global__ void colstats_kernel() {
    int j = blockIdx.x * blockDim.x + threadIdx.x;
    int i0 = blockIdx.y * ROWS_PER_CHUNK;
    float m = -CUDART_INF_F, s = 0.0f;
    const float* col = g_A + (size_t)i0 * HW + j;
    for (int i = 0; i < ROWS_PER_CHUNK; i++) {
        float v = col[(size_t)i * HW];
        float nm = fmaxf(m, v);
        s = s * __expf(m - nm) + __expf(v - nm);
        m = nm;
    }
    g_pm[blockIdx.y * HW + j] = m;
    g_ps[blockIdx.y * HW + j] = s;
}

// 5) Merge chunk partials; fold mask/beta/gama/colsum into per-column weights:
//    wb[j] = M[j]*beta[j]/colsum[j]  (softmax normalizer is over UNMASKED rows,
//    matching reference order softmax -> *M).
__global__ void mergestats_kernel() {
    int j = blockIdx.x * blockDim.x + threadIdx.x;
    float m = -CUDART_INF_F;
    for (int c = 0; c < NCHUNK; c++) m = fmaxf(m, g_pm[c * HW + j]);
    float s = 0.0f;
    for (int c = 0; c < NCHUNK; c++) s += g_ps[c * HW + j] * __expf(g_pm[c * HW + j] - m);
    g_colmax[j] = m;
    float inv = g_M[j] / s;
    g_wb[j] = g_beta[j] * inv;
    g_wg[j] = g_gama[j] * inv;
}

// 6) One warp per row: beta_hat[i] = sum_j exp(A[i,j]-colmax[j]) * wb[j], same for gama.
__global__ void rowsum_kernel() {
    int warp = (blockIdx.x * blockDim.x + threadIdx.x) >> 5;
    int lane = threadIdx.x & 31;
    const float* row = g_A + (size_t)warp * HW;
    float b = 0.0f, g = 0.0f;
    for (int j0 = lane * 4; j0 < HW; j0 += 128) {
        float4 v  = *(const float4*)(row + j0);
        float4 cm = *(const float4*)(g_colmax + j0);
        float4 wb = *(const float4*)(g_wb + j0);
        float4 wg = *(const float4*)(g_wg + j0);
        float e;
        e = __expf(v.x - cm.x); b = fmaf(e, wb.x, b); g = fmaf(e, wg.x, g);
        e = __expf(v.y - cm.y); b = fmaf(e, wb.y, b); g = fmaf(e, wg.y, g);
        e = __expf(v.z - cm.z); b = fmaf(e, wb.z, b); g = fmaf(e, wg.z, g);
        e = __expf(v.w - cm.w); b = fmaf(e, wb.w, b); g = fmaf(e, wg.w, g);
    }
#pragma unroll
    for (int o = 16; o > 0; o >>= 1) {
        b += __shfl_down_sync(0xFFFFFFFFu, b, o);
        g += __shfl_down_sync(0xFFFFFFFFu, g, o);
    }
    if (lane == 0) {
        g_bhat[warp] = b;
        g_ghat[warp] = g;
    }
}

// 7) out[c,p] = gama_hat[p]*feat_src[c,p] + beta_hat[p]
__global__ void finalize_kernel(const float* __restrict__ fs, float* __restrict__ out) {
    int t = blockIdx.x * blockDim.x + threadIdx.x;
    if (t >= NF) return;
    int p = t % HW;
    out[t] = fmaf(g_ghat[p], fs[t], g_bhat[p]);
}

extern "C" void kernel_launch(void* const* d_in, const int* in_sizes, int n_in,
                              void* d_out, int out_size) {
    const float* fs = (const float*)d_in[0];   // feat_src (1,256,96,96)
    const float* fr = (const float*)d_in[1];   // feat_ref
    const float* ls = (const float*)d_in[2];   // landmarks_src (1,136,96,96)
    const float* lr = (const float*)d_in[3];   // landmarks_ref
    const int*   ms = (const int*)d_in[4];     // mask_src (1,1,96,96)
    const int*   mr = (const int*)d_in[5];     // mask_ref
    const float* w1 = (const float*)d_in[6];
    const float* b1 = (const float*)d_in[7];
    const float* w2 = (const float*)d_in[8];
    const float* b2 = (const float*)d_in[9];
    float* out = (float*)d_out;

    prep_concat<<<(NTOT + 255) / 256, 256>>>(fs, fr, ls, lr);
    prep_betagama<<<(HW + 255) / 256, 256>>>(fr, ms, mr, w1, b1, w2, b2);

    dim3 gemm_grid(HW / 128, HW / 128);        // 72 x 72
    sgemm_kernel<<<gemm_grid, 256>>>();

    dim3 cs_grid(HW / 256, NCHUNK);            // 36 x 32
    colstats_kernel<<<cs_grid, 256>>>();
    mergestats_kernel<<<HW / 256, 256>>>();
    rowsum_kernel<<<(HW * 32) / 256, 256>>>(); // one warp per row
    finalize_kernel<<<(NF + 255) / 256, 256>>>(fs, out);
}

// round 7
// speedup vs baseline: 1.0002x; 1.0002x over previous
#include <cuda_runtime.h>
#include <math_constants.h>

#define HW 9216            // 96*96
#define CK 392             // 256 + 136
#define NF (256 * HW)      // visual-feature element count
#define NTOT (CK * HW)     // concat element count = 3612672
#define NCHUNK 32
#define ROWS_PER_CHUNK (HW / NCHUNK)   // 288

// ---- static device scratch (no dynamic allocation allowed) ----
__device__ __align__(16) float g_SRC[NTOT];                 // (9216, 392) row-major
__device__ __align__(16) float g_REF[NTOT];                 // (392, 9216) row-major
__device__ __align__(16) float g_A[(size_t)HW * HW];        // 340 MB logits
__device__ float g_pm[NCHUNK * HW];
__device__ float g_ps[NCHUNK * HW];
__device__ float g_beta[HW], g_gama[HW], g_M[HW];
__device__ float g_colmax[HW], g_wb[HW], g_wg[HW];
__device__ float g_bhat[HW], g_ghat[HW];

// 1) Build the flattened concat buffers. The torch/jax "raw reshape" of the
//    channel-concat is exactly the contiguous flat buffer, so SRC/REF become
//    plain row-major GEMM operands.
__global__ void prep_concat(const float* __restrict__ fs, const float* __restrict__ fr,
                            const float* __restrict__ ls, const float* __restrict__ lr) {
    int t = blockIdx.x * blockDim.x + threadIdx.x;
    if (t >= NTOT) return;
    if (t < NF) {
        g_SRC[t] = 0.01f * fs[t];
        g_REF[t] = 0.01f * fr[t];
    } else {
        g_SRC[t] = ls[t - NF];
        g_REF[t] = lr[t - NF];
    }
}

// 2) 1x1 convs (256->1) + mask equality vector.
__global__ void prep_betagama(const float* __restrict__ fr,
                              const int* __restrict__ ms, const int* __restrict__ mr,
                              const float* __restrict__ w1, const float* __restrict__ b1,
                              const float* __restrict__ w2, const float* __restrict__ b2) {
    int p = blockIdx.x * blockDim.x + threadIdx.x;
    if (p >= HW) return;
    float b = b1[0], g = b2[0];
#pragma unroll 8
    for (int c = 0; c < 256; c++) {
        float v = fr[c * HW + p];          // coalesced across p
        b = fmaf(v, w1[c], b);
        g = fmaf(v, w2[c], g);
    }
    g_beta[p] = b;
    g_gama[p] = g;
    g_M[p] = (ms[p] == mr[p]) ? 1.0f : 0.0f;
}

// 3) fp32 SGEMM: g_A = g_SRC (9216x392) @ g_REF (392x9216).
//    128x128 block tile, BK=8, 256 threads, 8x8 per thread (split 4+4 to keep
//    LDS.128 conflict-free). K=392 = 49*8, M=N divisible by 128: no bounds checks.
__global__ void __launch_bounds__(256) sgemm_kernel() {
    __shared__ __align__(16) float As[8][128];
    __shared__ __align__(16) float Bs[8][128];
    const int tid = threadIdx.x;
    const int tx = tid & 15;        // 0..15  -> N direction
    const int ty = tid >> 4;        // 0..15  -> M direction
    const float* Ab = g_SRC + (size_t)blockIdx.y * 128 * CK;
    const float* Bb = g_REF + (size_t)blockIdx.x * 128;

    const int arow = tid >> 1, acol = (tid & 1) * 4;   // A: 128 rows x 8 k, float4/thread
    const int brow = tid >> 5, bcol = (tid & 31) * 4;  // B: 8 k x 128 cols, float4/thread

    float acc[8][8];
#pragma unroll
    for (int i = 0; i < 8; i++)
#pragma unroll
        for (int j = 0; j < 8; j++) acc[i][j] = 0.0f;

    for (int k0 = 0; k0 < CK; k0 += 8) {
        float4 av = *(const float4*)(Ab + (size_t)arow * CK + k0 + acol);
        float4 bv = *(const float4*)(Bb + (size_t)(k0 + brow) * HW + bcol);
        __syncthreads();
        As[acol + 0][arow] = av.x;
        As[acol + 1][arow] = av.y;
        As[acol + 2][arow] = av.z;
        As[acol + 3][arow] = av.w;
        *(float4*)&Bs[brow][bcol] = bv;
        __syncthreads();
#pragma unroll
        for (int k = 0; k < 8; k++) {
            float4 a0 = *(const float4*)&As[k][ty * 4];
            float4 a1 = *(const float4*)&As[k][ty * 4 + 64];
            float4 b0 = *(const float4*)&Bs[k][tx * 4];
            float4 b1 = *(const float4*)&Bs[k][tx * 4 + 64];
            float ar[8] = {a0.x, a0.y, a0.z, a0.w, a1.x, a1.y, a1.z, a1.w};
            float br[8] = {b0.x, b0.y, b0.z, b0.w, b1.x, b1.y, b1.z, b1.w};
#pragma unroll
            for (int i = 0; i < 8; i++)
#pragma unroll
                for (int j = 0; j < 8; j++) acc[i][j] = fmaf(ar[i], br[j], acc[i][j]);
        }
    }

    const size_t crow0 = (size_t)blockIdx.y * 128 + ty * 4;
    const size_t ccol0 = (size_t)blockIdx.x * 128 + tx * 4;
#pragma unroll
    for (int i = 0; i < 8; i++) {
        size_t r = crow0 + (i & 3) + (i >> 2) * 64;
        float* Cp = g_A + r * HW + ccol0;
        *(float4*)Cp        = make_float4(acc[i][0], acc[i][1], acc[i][2], acc[i][3]);
        *(float4*)(Cp + 64) = make_float4(acc[i][4], acc[i][5], acc[i][6], acc[i][7]);
    }
}

// 4) Per-column online (max, sum-exp) over a 288-row chunk. Thread = one column,
//    consecutive threads = consecutive columns -> fully coalesced A reads.
__global__ void colstats_kernel() {
    int j = blockIdx.x * blockDim.x + threadIdx.x;
    int i0 = blockIdx.y * ROWS_PER_CHUNK;
    float m = -CUDART_INF_F, s = 0.0f;
    const float* col = g_A + (size_t)i0 * HW + j;
    for (int i = 0; i < ROWS_PER_CHUNK; i++) {
        float v = col[(size_t)i * HW];
        float nm = fmaxf(m, v);
        s = s * __expf(m - nm) + __expf(v - nm);
        m = nm;
    }
    g_pm[blockIdx.y * HW + j] = m;
    g_ps[blockIdx.y * HW + j] = s;
}

// 5) Merge chunk partials; fold mask/beta/gama/colsum into per-column weights:
//    wb[j] = M[j]*beta[j]/colsum[j]  (softmax normalizer is over UNMASKED rows,
//    matching reference order softmax -> *M).
__global__ void mergestats_kernel() {
    int j = blockIdx.x * blockDim.x + threadIdx.x;
    float m = -CUDART_INF_F;
    for (int c = 0; c < NCHUNK; c++) m = fmaxf(m, g_pm[c * HW + j]);
    float s = 0.0f;
    for (int c = 0; c < NCHUNK; c++) s += g_ps[c * HW + j] * __expf(g_pm[c * HW + j] - m);
    g_colmax[j] = m;
    float inv = g_M[j] / s;
    g_wb[j] = g_beta[j] * inv;
    g_wg[j] = g_gama[j] * inv;
}

// 6) One warp per row: beta_hat[i] = sum_j exp(A[i,j]-colmax[j]) * wb[j], same for gama.
__global__ void rowsum_kernel() {
    int warp = (blockIdx.x * blockDim.x + threadIdx.x) >> 5;
    int lane = threadIdx.x & 31;
    const float* row = g_A + (size_t)warp * HW;
    float b = 0.0f, g = 0.0f;
    for (int j0 = lane * 4; j0 < HW; j0 += 128) {
        float4 v  = *(const float4*)(row + j0);
        float4 cm = *(const float4*)(g_colmax + j0);
        float4 wb = *(const float4*)(g_wb + j0);
        float4 wg = *(const float4*)(g_wg + j0);
        float e;
        e = __expf(v.x - cm.x); b = fmaf(e, wb.x, b); g = fmaf(e, wg.x, g);
        e = __expf(v.y - cm.y); b = fmaf(e, wb.y, b); g = fmaf(e, wg.y, g);
        e = __expf(v.z - cm.z); b = fmaf(e, wb.z, b); g = fmaf(e, wg.z, g);
        e = __expf(v.w - cm.w); b = fmaf(e, wb.w, b); g = fmaf(e, wg.w, g);
    }
#pragma unroll
    for (int o = 16; o > 0; o >>= 1) {
        b += __shfl_down_sync(0xFFFFFFFFu, b, o);
        g += __shfl_down_sync(0xFFFFFFFFu, g, o);
    }
    if (lane == 0) {
        g_bhat[warp] = b;
        g_ghat[warp] = g;
    }
}

// 7) out[c,p] = gama_hat[p]*feat_src[c,p] + beta_hat[p]
__global__ void finalize_kernel(const float* __restrict__ fs, float* __restrict__ out) {
    int t = blockIdx.x * blockDim.x + threadIdx.x;
    if (t >= NF) return;
    int p = t % HW;
    out[t] = fmaf(g_ghat[p], fs[t], g_bhat[p]);
}

extern "C" void kernel_launch(void* const* d_in, const int* in_sizes, int n_in,
                              void* d_out, int out_size) {
    const float* fs = (const float*)d_in[0];   // feat_src (1,256,96,96)
    const float* fr = (const float*)d_in[1];   // feat_ref
    const float* ls = (const float*)d_in[2];   // landmarks_src (1,136,96,96)
    const float* lr = (const float*)d_in[3];   // landmarks_ref
    const int*   ms = (const int*)d_in[4];     // mask_src (1,1,96,96)
    const int*   mr = (const int*)d_in[5];     // mask_ref
    const float* w1 = (const float*)d_in[6];
    const float* b1 = (const float*)d_in[7];
    const float* w2 = (const float*)d_in[8];
    const float* b2 = (const float*)d_in[9];
    float* out = (float*)d_out;

    prep_concat<<<(NTOT + 255) / 256, 256>>>(fs, fr, ls, lr);
    prep_betagama<<<(HW + 255) / 256, 256>>>(fr, ms, mr, w1, b1, w2, b2);

    dim3 gemm_grid(HW / 128, HW / 128);        // 72 x 72
    sgemm_kernel<<<gemm_grid, 256>>>();

    dim3 cs_grid(HW / 256, NCHUNK);            // 36 x 32
    colstats_kernel<<<cs_grid, 256>>>();
    mergestats_kernel<<<HW / 256, 256>>>();
    rowsum_kernel<<<(HW * 32) / 256, 256>>>(); // one warp per row
    finalize_kernel<<<(NF + 255) / 256, 256>>>(fs, out);
}

// round 8
// speedup vs baseline: 1.1175x; 1.1173x over previous
#include <cuda_runtime.h>
#include <math_constants.h>

#define HW 9216            // 96*96
#define CK 392             // 256 + 136
#define NF (256 * HW)      // visual-feature element count
#define NTOT (CK * HW)     // concat element count = 3612672
#define NCHUNK 32
#define ROWS_PER_CHUNK (HW / NCHUNK)   // 288

typedef unsigned long long ull;

// packed fp32x2 FMA (sm_103a): two IEEE fp32 FMAs per instruction on the fma pipe.
__device__ __forceinline__ ull fma2(ull a, ull b, ull c) {
    ull d;
    asm("fma.rn.f32x2 %0, %1, %2, %3;" : "=l"(d) : "l"(a), "l"(b), "l"(c));
    return d;
}
__device__ __forceinline__ ull pack2(float x) {
    ull r;
    asm("mov.b64 %0, {%1, %1};" : "=l"(r) : "f"(x));
    return r;
}

// ---- static device scratch (no dynamic allocation allowed) ----
__device__ __align__(16) float g_SRC[NTOT];                 // (9216, 392) row-major
__device__ __align__(16) float g_REF[NTOT];                 // (392, 9216) row-major
__device__ __align__(16) float g_A[(size_t)HW * HW];        // 340 MB logits
__device__ float g_pm[NCHUNK * HW];
__device__ float g_ps[NCHUNK * HW];
__device__ float g_beta[HW], g_gama[HW], g_M[HW];
__device__ float g_colmax[HW], g_wb[HW], g_wg[HW];
__device__ float g_bhat[HW], g_ghat[HW];

// 1) Build the flattened concat buffers (raw reshape of channel-concat == flat buffer).
__global__ void prep_concat(const float* __restrict__ fs, const float* __restrict__ fr,
                            const float* __restrict__ ls, const float* __restrict__ lr) {
    int t = blockIdx.x * blockDim.x + threadIdx.x;
    if (t >= NTOT) return;
    if (t < NF) {
        g_SRC[t] = 0.01f * fs[t];
        g_REF[t] = 0.01f * fr[t];
    } else {
        g_SRC[t] = ls[t - NF];
        g_REF[t] = lr[t - NF];
    }
}

// 2) 1x1 convs (256->1) + mask equality vector.
__global__ void prep_betagama(const float* __restrict__ fr,
                              const int* __restrict__ ms, const int* __restrict__ mr,
                              const float* __restrict__ w1, const float* __restrict__ b1,
                              const float* __restrict__ w2, const float* __restrict__ b2) {
    int p = blockIdx.x * blockDim.x + threadIdx.x;
    if (p >= HW) return;
    float b = b1[0], g = b2[0];
#pragma unroll 8
    for (int c = 0; c < 256; c++) {
        float v = fr[c * HW + p];          // coalesced across p
        b = fmaf(v, w1[c], b);
        g = fmaf(v, w2[c], g);
    }
    g_beta[p] = b;
    g_gama[p] = g;
    g_M[p] = (ms[p] == mr[p]) ? 1.0f : 0.0f;
}

// 3) fp32 SGEMM via packed fma.rn.f32x2: g_A = g_SRC (9216x392) @ g_REF (392x9216).
//    128x128 block tile, BK=8, 256 threads, 8 rows x 4 col-pairs per thread.
//    B column-pairs load as native 64-bit packed operands from Bs (contiguous j);
//    A values are broadcast-packed with one mov.b64 per row per k (hidden on ALU pipe).
__global__ void __launch_bounds__(256, 2) sgemm_kernel() {
    __shared__ __align__(16) float As[8][128];
    __shared__ __align__(16) float Bs[8][128];
    const int tid = threadIdx.x;
    const int tx = tid & 15;        // 0..15  -> N direction
    const int ty = tid >> 4;        // 0..15  -> M direction
    const float* Ab = g_SRC + (size_t)blockIdx.y * 128 * CK;
    const float* Bb = g_REF + (size_t)blockIdx.x * 128;

    const int arow = tid >> 1, acol = (tid & 1) * 4;   // A: 128 rows x 8 k
    const int brow = tid >> 5, bcol = (tid & 31) * 4;  // B: 8 k x 128 cols

    ull acc[8][4];                  // [row][col-pair], lanes = (col, col+1)
#pragma unroll
    for (int i = 0; i < 8; i++)
#pragma unroll
        for (int j = 0; j < 4; j++) acc[i][j] = 0ull;

    // register prefetch of first tile
    float4 av = *(const float4*)(Ab + (size_t)arow * CK + acol);
    float4 bv = *(const float4*)(Bb + (size_t)brow * HW + bcol);

    for (int k0 = 0; k0 < CK; k0 += 8) {
        __syncthreads();
        As[acol + 0][arow] = av.x;
        As[acol + 1][arow] = av.y;
        As[acol + 2][arow] = av.z;
        As[acol + 3][arow] = av.w;
        *(float4*)&Bs[brow][bcol] = bv;
        __syncthreads();
        if (k0 + 8 < CK) {          // prefetch next tile while computing this one
            av = *(const float4*)(Ab + (size_t)arow * CK + (k0 + 8) + acol);
            bv = *(const float4*)(Bb + (size_t)(k0 + 8 + brow) * HW + bcol);
        }
#pragma unroll
        for (int k = 0; k < 8; k++) {
            float4 a0 = *(const float4*)&As[k][ty * 4];
            float4 a1 = *(const float4*)&As[k][ty * 4 + 64];
            const ull* bp0 = (const ull*)&Bs[k][tx * 4];        // (b0,b1),(b2,b3)
            const ull* bp1 = (const ull*)&Bs[k][tx * 4 + 64];   // (+64 cols)
            ull b2[4] = {bp0[0], bp0[1], bp1[0], bp1[1]};
            float ar[8] = {a0.x, a0.y, a0.z, a0.w, a1.x, a1.y, a1.z, a1.w};
#pragma unroll
            for (int i = 0; i < 8; i++) {
                ull ad = pack2(ar[i]);
#pragma unroll
                for (int j = 0; j < 4; j++)
                    acc[i][j] = fma2(ad, b2[j], acc[i][j]);
            }
        }
    }

    const size_t crow0 = (size_t)blockIdx.y * 128 + ty * 4;
    const size_t ccol0 = (size_t)blockIdx.x * 128 + tx * 4;
#pragma unroll
    for (int i = 0; i < 8; i++) {
        size_t r = crow0 + (i & 3) + (i >> 2) * 64;
        float* Cp = g_A + r * HW + ccol0;
        ulonglong2 t0, t1;
        t0.x = acc[i][0]; t0.y = acc[i][1];   // cols tx*4 .. tx*4+3 (in order)
        t1.x = acc[i][2]; t1.y = acc[i][3];   // cols +64
        *(ulonglong2*)Cp        = t0;
        *(ulonglong2*)(Cp + 64) = t1;
    }
}

// 4) Per-column online (max, sum-exp) over a 288-row chunk (coalesced A reads).
__global__ void colstats_kernel() {
    int j = blockIdx.x * blockDim.x + threadIdx.x;
    int i0 = blockIdx.y * ROWS_PER_CHUNK;
    float m = -CUDART_INF_F, s = 0.0f;
    const float* col = g_A + (size_t)i0 * HW + j;
    for (int i = 0; i < ROWS_PER_CHUNK; i++) {
        float v = col[(size_t)i * HW];
        float nm = fmaxf(m, v);
        s = s * __expf(m - nm) + __expf(v - nm);
        m = nm;
    }
    g_pm[blockIdx.y * HW + j] = m;
    g_ps[blockIdx.y * HW + j] = s;
}

// 5) Merge chunk partials; fold mask/beta/gama/colsum into per-column weights.
__global__ void mergestats_kernel() {
    int j = blockIdx.x * blockDim.x + threadIdx.x;
    float m = -CUDART_INF_F;
    for (int c = 0; c < NCHUNK; c++) m = fmaxf(m, g_pm[c * HW + j]);
    float s = 0.0f;
    for (int c = 0; c < NCHUNK; c++) s += g_ps[c * HW + j] * __expf(g_pm[c * HW + j] - m);
    g_colmax[j] = m;
    float inv = g_M[j] / s;
    g_wb[j] = g_beta[j] * inv;
    g_wg[j] = g_gama[j] * inv;
}

// 6) One warp per row: beta_hat[i] = sum_j exp(A[i,j]-colmax[j]) * wb[j], same for gama.
__global__ void rowsum_kernel() {
    int warp = (blockIdx.x * blockDim.x + threadIdx.x) >> 5;
    int lane = threadIdx.x & 31;
    const float* row = g_A + (size_t)warp * HW;
    float b = 0.0f, g = 0.0f;
    for (int j0 = lane * 4; j0 < HW; j0 += 128) {
        float4 v  = *(const float4*)(row + j0);
        float4 cm = *(const float4*)(g_colmax + j0);
        float4 wb = *(const float4*)(g_wb + j0);
        float4 wg = *(const float4*)(g_wg + j0);
        float e;
        e = __expf(v.x - cm.x); b = fmaf(e, wb.x, b); g = fmaf(e, wg.x, g);
        e = __expf(v.y - cm.y); b = fmaf(e, wb.y, b); g = fmaf(e, wg.y, g);
        e = __expf(v.z - cm.z); b = fmaf(e, wb.z, b); g = fmaf(e, wg.z, g);
        e = __expf(v.w - cm.w); b = fmaf(e, wb.w, b); g = fmaf(e, wg.w, g);
    }
#pragma unroll
    for (int o = 16; o > 0; o >>= 1) {
        b += __shfl_down_sync(0xFFFFFFFFu, b, o);
        g += __shfl_down_sync(0xFFFFFFFFu, g, o);
    }
    if (lane == 0) {
        g_bhat[warp] = b;
        g_ghat[warp] = g;
    }
}

// 7) out[c,p] = gama_hat[p]*feat_src[c,p] + beta_hat[p]
__global__ void finalize_kernel(const float* __restrict__ fs, float* __restrict__ out) {
    int t = blockIdx.x * blockDim.x + threadIdx.x;
    if (t >= NF) return;
    int p = t % HW;
    out[t] = fmaf(g_ghat[p], fs[t], g_bhat[p]);
}

extern "C" void kernel_launch(void* const* d_in, const int* in_sizes, int n_in,
                              void* d_out, int out_size) {
    const float* fs = (const float*)d_in[0];   // feat_src (1,256,96,96)
    const float* fr = (const float*)d_in[1];   // feat_ref
    const float* ls = (const float*)d_in[2];   // landmarks_src (1,136,96,96)
    const float* lr = (const float*)d_in[3];   // landmarks_ref
    const int*   ms = (const int*)d_in[4];     // mask_src (1,1,96,96)
    const int*   mr = (const int*)d_in[5];     // mask_ref
    const float* w1 = (const float*)d_in[6];
    const float* b1 = (const float*)d_in[7];
    const float* w2 = (const float*)d_in[8];
    const float* b2 = (const float*)d_in[9];
    float* out = (float*)d_out;

    prep_concat<<<(NTOT + 255) / 256, 256>>>(fs, fr, ls, lr);
    prep_betagama<<<(HW + 255) / 256, 256>>>(fr, ms, mr, w1, b1, w2, b2);

    dim3 gemm_grid(HW / 128, HW / 128);        // 72 x 72
    sgemm_kernel<<<gemm_grid, 256>>>();

    dim3 cs_grid(HW / 256, NCHUNK);            // 36 x 32
    colstats_kernel<<<cs_grid, 256>>>();
    mergestats_kernel<<<HW / 256, 256>>>();
    rowsum_kernel<<<(HW * 32) / 256, 256>>>(); // one warp per row
    finalize_kernel<<<(NF + 255) / 256, 256>>>(fs, out);
}

// round 10
// speedup vs baseline: 2.0676x; 1.8501x over previous
#include <cuda_runtime.h>
#include <cuda_bf16.h>
#include <math_constants.h>
#include <cstdint>

#define HW 9216            // 96*96
#define CK 392             // 256 + 136
#define NF (256 * HW)
#define KSEG 416           // one split segment, 13 chunks of 32
#define KBIG 1248          // 3 segments: [Ah|Ah|Al] x [Bh|Bl|Bh]
#define NCHKS 39           // KBIG / 32
#define NCHUNK 32
#define ROWS_PER_CHUNK (HW / NCHUNK)   // 288

// ===================== static device scratch =====================
__device__ __align__(16) __nv_bfloat16 g_Abig[(size_t)HW * KBIG]; // (9216,1248) K-major
__device__ __align__(16) __nv_bfloat16 g_Bbig[(size_t)HW * KBIG]; // transposed (n,k) K-major
__device__ __align__(16) float g_A[(size_t)HW * HW];              // 340 MB logits
__device__ float g_pm[NCHUNK * HW];
__device__ float g_ps[NCHUNK * HW];
__device__ float g_beta[HW], g_gama[HW], g_M[HW];
__device__ float g_colmax[HW], g_wb[HW], g_wg[HW];
__device__ float g_bhat[HW], g_ghat[HW];

// ===================== PTX helpers (non-'a' features only) =====================
__device__ __forceinline__ uint32_t smem_u32(const void* p) {
    uint32_t a;
    asm("{ .reg .u64 t; cvta.to.shared.u64 t, %1; cvt.u32.u64 %0, t; }" : "=r"(a) : "l"(p));
    return a;
}
__device__ __forceinline__ void cp16(uint32_t saddr, const void* g) {
    asm volatile("cp.async.cg.shared.global [%0], [%1], 16;" :: "r"(saddr), "l"(g));
}
#define CP_COMMIT() asm volatile("cp.async.commit_group;" ::: "memory")
#define CP_WAIT(n)  asm volatile("cp.async.wait_group %0;" :: "n"(n) : "memory")
#define LDSM_X4(r0, r1, r2, r3, addr) \
    asm volatile("ldmatrix.sync.aligned.m8n8.x4.shared.b16 {%0,%1,%2,%3}, [%4];" \
        : "=r"(r0), "=r"(r1), "=r"(r2), "=r"(r3) : "r"(addr))
#define MMA16816(d, a, b) \
    asm volatile("mma.sync.aligned.m16n8k16.row.col.f32.bf16.bf16.f32 " \
        "{%0,%1,%2,%3}, {%4,%5,%6,%7}, {%8,%9}, {%0,%1,%2,%3};" \
        : "+f"((d)[0]), "+f"((d)[1]), "+f"((d)[2]), "+f"((d)[3]) \
        : "r"((a)[0]), "r"((a)[1]), "r"((a)[2]), "r"((a)[3]), "r"((b)[0]), "r"((b)[1]))

// smem tile layout: [128 rows][32 bf16] = 64B rows; 16B-chunk swizzle c ^= (r>>1)&3
__device__ __forceinline__ uint32_t swz(int r, int c) {
    return (uint32_t)(r * 64 + ((c ^ ((r >> 1) & 3)) << 4));
}

// 1a) A' hi/lo: x(m,k) = flat_src[m*392+k], flat_src = [0.01*fs ; ls].
//     seg0 = hi, seg1 = hi, seg2 = lo.
__global__ void prep_src_bf16(const float* __restrict__ fs, const float* __restrict__ ls) {
    int t = blockIdx.x * blockDim.x + threadIdx.x;
    if (t >= HW * KSEG) return;
    int m = t / KSEG, kp = t - m * KSEG;
    float x = 0.0f;
    if (kp < CK) {
        int s = m * CK + kp;
        x = (s < NF) ? 0.01f * fs[s] : ls[s - NF];
    }
    __nv_bfloat16 h = __float2bfloat16(x);
    __nv_bfloat16 l = __float2bfloat16(x - __bfloat162float(h));
    size_t o = (size_t)m * KBIG + kp;
    g_Abig[o] = h;
    g_Abig[o + KSEG] = h;
    g_Abig[o + 2 * KSEG] = l;
}

// 1b) B' transposed hi/lo: x(n,k) = REF[k][n] = (k<256 ? 0.01*fr[k*HW+n] : lr[(k-256)*HW+n]).
//     seg0 = hi, seg1 = lo, seg2 = hi.
__global__ void prep_ref_bf16(const float* __restrict__ fr, const float* __restrict__ lr) {
    __shared__ float tile[32][33];
    int k0 = blockIdx.y * 32, n0 = blockIdx.x * 32;
    int tx = threadIdx.x, ty = threadIdx.y;   // (32, 8)
#pragma unroll
    for (int i = 0; i < 32; i += 8) {
        int k = k0 + ty + i, n = n0 + tx;
        float x = 0.0f;
        if (k < CK) x = (k < 256) ? 0.01f * fr[k * HW + n] : lr[(k - 256) * HW + n];
        tile[ty + i][tx] = x;
    }
    __syncthreads();
#pragma unroll
    for (int i = 0; i < 32; i += 8) {
        int n = n0 + ty + i, k = k0 + tx;
        float x = tile[tx][ty + i];
        __nv_bfloat16 h = __float2bfloat16(x);
        __nv_bfloat16 l = __float2bfloat16(x - __bfloat162float(h));
        size_t o = (size_t)n * KBIG + k;
        g_Bbig[o] = h;
        g_Bbig[o + KSEG] = l;
        g_Bbig[o + 2 * KSEG] = h;
    }
}

// 2) 1x1 convs (256->1) + mask equality vector.
__global__ void prep_betagama(const float* __restrict__ fr,
                              const int* __restrict__ ms, const int* __restrict__ mr,
                              const float* __restrict__ w1, const float* __restrict__ b1,
                              const float* __restrict__ w2, const float* __restrict__ b2) {
    int p = blockIdx.x * blockDim.x + threadIdx.x;
    if (p >= HW) return;
    float b = b1[0], g = b2[0];
#pragma unroll 8
    for (int c = 0; c < 256; c++) {
        float v = fr[c * HW + p];
        b = fmaf(v, w1[c], b);
        g = fmaf(v, w2[c], g);
    }
    g_beta[p] = b;
    g_gama[p] = g;
    g_M[p] = (ms[p] == mr[p]) ? 1.0f : 0.0f;
}

// 3) bf16 HMMA GEMM: g_A = A'(9216x1248) @ B'^T, fp32 accum.
//    128x128 CTA tile, BK=32, 8 warps of 32x64, cp.async double-buffered.
__global__ void __launch_bounds__(256, 2) gemm_hmma_kernel() {
    __shared__ __align__(128) __nv_bfloat16 sA[2][128 * 32];
    __shared__ __align__(128) __nv_bfloat16 sB[2][128 * 32];
    const int tid = threadIdx.x;
    const int wid = tid >> 5, lane = tid & 31;
    const size_t m0 = (size_t)blockIdx.y * 128;
    const size_t n0 = (size_t)blockIdx.x * 128;
    const int mw = (wid & 3) * 32;   // warp m offset in tile
    const int nw = (wid >> 2) * 64;  // warp n offset in tile
    const uint32_t sAu = smem_u32(sA), sBu = smem_u32(sB);

    // per-thread load slots: 16B chunks s = tid and tid+256; r = s/4, c = s%4
    const int lr0 = tid >> 2, lc0 = tid & 3;
    const int lr1 = (tid + 256) >> 2, lc1 = lc0;
    const uint32_t sa0 = swz(lr0, lc0), sa1 = swz(lr1, lc1);
    const __nv_bfloat16* gA0 = g_Abig + (m0 + lr0) * KBIG + lc0 * 8;
    const __nv_bfloat16* gA1 = g_Abig + (m0 + lr1) * KBIG + lc1 * 8;
    const __nv_bfloat16* gB0 = g_Bbig + (n0 + lr0) * KBIG + lc0 * 8;
    const __nv_bfloat16* gB1 = g_Bbig + (n0 + lr1) * KBIG + lc1 * 8;

    float acc[2][8][4];
#pragma unroll
    for (int i = 0; i < 2; i++)
#pragma unroll
        for (int j = 0; j < 8; j++)
#pragma unroll
            for (int q = 0; q < 4; q++) acc[i][j][q] = 0.0f;

    // ldmatrix addresses (fixed per thread, swizzled)
    // A x4: lanes 0-7: m-low/c-low; 8-15: m-high/c-low; 16-23: m-low/c-high; 24-31: m-high/c-high
    const int a_r = (lane & 7) + ((lane >> 3) & 1) * 8;
    const int a_c = lane >> 4;
    // B x4 (covers n-subtiles 2t,2t+1): 0-7: n-low/c-low; 8-15: n-low/c-high; 16-23: n-high/c-low; 24-31: n-high/c-high
    const int b_r = (lane & 7) + (lane >> 4) * 8;
    const int b_c = (lane >> 3) & 1;

    // prefetch chunk 0
    {
        cp16(sAu + sa0, gA0); cp16(sAu + sa1, gA1);
        cp16(sBu + sa0, gB0); cp16(sBu + sa1, gB1);
        CP_COMMIT();
    }

    for (int ch = 0; ch < NCHKS; ++ch) {
        const int buf = ch & 1;
        if (ch + 1 < NCHKS) {
            const uint32_t off = (uint32_t)(buf ^ 1) * 8192;
            const size_t kofs = (size_t)(ch + 1) * 32;
            cp16(sAu + off + sa0, gA0 + kofs); cp16(sAu + off + sa1, gA1 + kofs);
            cp16(sBu + off + sa0, gB0 + kofs); cp16(sBu + off + sa1, gB1 + kofs);
            CP_COMMIT();
            CP_WAIT(1);
        } else {
            CP_WAIT(0);
        }
        __syncthreads();

        const uint32_t ab = sAu + (uint32_t)buf * 8192;
        const uint32_t bb = sBu + (uint32_t)buf * 8192;
#pragma unroll
        for (int ks = 0; ks < 2; ++ks) {
            uint32_t afr[2][4], bfr[8][2];
#pragma unroll
            for (int mt = 0; mt < 2; ++mt) {
                int r = mw + mt * 16 + a_r;
                LDSM_X4(afr[mt][0], afr[mt][1], afr[mt][2], afr[mt][3],
                        ab + swz(r, 2 * ks + a_c));
            }
#pragma unroll
            for (int np = 0; np < 4; ++np) {
                int r = nw + np * 16 + b_r;
                LDSM_X4(bfr[np * 2][0], bfr[np * 2][1], bfr[np * 2 + 1][0], bfr[np * 2 + 1][1],
                        bb + swz(r, 2 * ks + b_c));
            }
#pragma unroll
            for (int mt = 0; mt < 2; ++mt)
#pragma unroll
                for (int nt = 0; nt < 8; ++nt)
                    MMA16816(acc[mt][nt], afr[mt], bfr[nt]);
        }
        __syncthreads();
    }

    // epilogue: direct stores (lane layout: c0c1 at (m=lane/4, n=2*(lane%4)), c2c3 at m+8)
    const size_t mbase = m0 + mw + (lane >> 2);
    const size_t nbase = n0 + nw + 2 * (lane & 3);
#pragma unroll
    for (int mt = 0; mt < 2; ++mt) {
#pragma unroll
        for (int nt = 0; nt < 8; ++nt) {
            size_t m = mbase + mt * 16;
            size_t n = nbase + nt * 8;
            float2 lo = make_float2(acc[mt][nt][0], acc[mt][nt][1]);
            float2 hi = make_float2(acc[mt][nt][2], acc[mt][nt][3]);
            *(float2*)&g_A[m * HW + n] = lo;
            *(float2*)&g_A[(m + 8) * HW + n] = hi;
        }
    }
}

// 4) Per-column online (max, sum-exp) over a 288-row chunk (coalesced A reads).
__global__ void colstats_kernel() {
    int j = blockIdx.x * blockDim.x + threadIdx.x;
    int i0 = blockIdx.y * ROWS_PER_CHUNK;
    float m = -CUDART_INF_F, s = 0.0f;
    const float* col = g_A + (size_t)i0 * HW + j;
    for (int i = 0; i < ROWS_PER_CHUNK; i++) {
        float v = col[(size_t)i * HW];
        float nm = fmaxf(m, v);
        s = s * __expf(m - nm) + __expf(v - nm);
        m = nm;
    }
    g_pm[blockIdx.y * HW + j] = m;
    g_ps[blockIdx.y * HW + j] = s;
}

// 5) Merge chunk partials; fold mask/beta/gama/colsum into per-column weights.
__global__ void mergestats_kernel() {
    int j = blockIdx.x * blockDim.x + threadIdx.x;
    float m = -CUDART_INF_F;
    for (int c = 0; c < NCHUNK; c++) m = fmaxf(m, g_pm[c * HW + j]);
    float s = 0.0f;
    for (int c = 0; c < NCHUNK; c++) s += g_ps[c * HW + j] * __expf(g_pm[c * HW + j] - m);
    g_colmax[j] = m;
    float inv = g_M[j] / s;
    g_wb[j] = g_beta[j] * inv;
    g_wg[j] = g_gama[j] * inv;
}

// 6) One warp per row: beta_hat[i] = sum_j exp(A[i,j]-colmax[j]) * wb[j], same for gama.
__global__ void rowsum_kernel() {
    int warp = (blockIdx.x * blockDim.x + threadIdx.x) >> 5;
    int lane = threadIdx.x & 31;
    const float* row = g_A + (size_t)warp * HW;
    float b = 0.0f, g = 0.0f;
    for (int j0 = lane * 4; j0 < HW; j0 += 128) {
        float4 v  = *(const float4*)(row + j0);
        float4 cm = *(const float4*)(g_colmax + j0);
        float4 wb = *(const float4*)(g_wb + j0);
        float4 wg = *(const float4*)(g_wg + j0);
        float e;
        e = __expf(v.x - cm.x); b = fmaf(e, wb.x, b); g = fmaf(e, wg.x, g);
        e = __expf(v.y - cm.y); b = fmaf(e, wb.y, b); g = fmaf(e, wg.y, g);
        e = __expf(v.z - cm.z); b = fmaf(e, wb.z, b); g = fmaf(e, wg.z, g);
        e = __expf(v.w - cm.w); b = fmaf(e, wb.w, b); g = fmaf(e, wg.w, g);
    }
#pragma unroll
    for (int o = 16; o > 0; o >>= 1) {
        b += __shfl_down_sync(0xFFFFFFFFu, b, o);
        g += __shfl_down_sync(0xFFFFFFFFu, g, o);
    }
    if (lane == 0) { g_bhat[warp] = b; g_ghat[warp] = g; }
}

// 7) out[c,p] = gama_hat[p]*feat_src[c,p] + beta_hat[p]
__global__ void finalize_kernel(const float* __restrict__ fs, float* __restrict__ out) {
    int t = blockIdx.x * blockDim.x + threadIdx.x;
    if (t >= NF) return;
    int p = t % HW;
    out[t] = fmaf(g_ghat[p], fs[t], g_bhat[p]);
}

extern "C" void kernel_launch(void* const* d_in, const int* in_sizes, int n_in,
                              void* d_out, int out_size) {
    const float* fs = (const float*)d_in[0];
    const float* fr = (const float*)d_in[1];
    const float* ls = (const float*)d_in[2];
    const float* lr = (const float*)d_in[3];
    const int*   ms = (const int*)d_in[4];
    const int*   mr = (const int*)d_in[5];
    const float* w1 = (const float*)d_in[6];
    const float* b1 = (const float*)d_in[7];
    const float* w2 = (const float*)d_in[8];
    const float* b2 = (const float*)d_in[9];
    float* out = (float*)d_out;

    prep_src_bf16<<<(HW * KSEG + 255) / 256, 256>>>(fs, ls);
    dim3 trg(HW / 32, KSEG / 32);
    prep_ref_bf16<<<trg, dim3(32, 8)>>>(fr, lr);
    prep_betagama<<<(HW + 255) / 256, 256>>>(fr, ms, mr, w1, b1, w2, b2);

    dim3 gemm_grid(HW / 128, HW / 128);        // 72 x 72
    gemm_hmma_kernel<<<gemm_grid, 256>>>();

    dim3 cs_grid(HW / 256, NCHUNK);            // 36 x 32
    colstats_kernel<<<cs_grid, 256>>>();
    mergestats_kernel<<<HW / 256, 256>>>();
    rowsum_kernel<<<(HW * 32) / 256, 256>>>();
    finalize_kernel<<<(NF + 255) / 256, 256>>>(fs, out);
}

// round 11
// speedup vs baseline: 2.8565x; 1.3816x over previous
#include <cuda_runtime.h>
#include <cuda_bf16.h>
#include <math_constants.h>
#include <cstdint>

#define HW 9216            // 96*96
#define CK 392             // 256 + 136
#define NF (256 * HW)
#define KSEG 416           // full-K hi segment (13 chunks of 32)
#define KLM 160            // landmark cross segment (136 padded to 160)
#define KBIG 736           // [Ah_full | Ah_lm | Al_lm] x [Bh_full | Bl_lm | Bh_lm]
#define NCHKS 23           // KBIG / 32
#define NCHUNK 32
#define ROWS_PER_CHUNK (HW / NCHUNK)   // 288

// ===================== static device scratch =====================
__device__ __align__(16) __nv_bfloat16 g_Abig[(size_t)HW * KBIG]; // (9216,736) K-major
__device__ __align__(16) __nv_bfloat16 g_Bbig[(size_t)HW * KBIG]; // transposed (n,k) K-major
__device__ __align__(16) float g_A[(size_t)HW * HW];              // 340 MB logits
__device__ float g_pm[NCHUNK * HW];
__device__ float g_ps[NCHUNK * HW];
__device__ float g_beta[HW], g_gama[HW], g_M[HW];
__device__ float g_colmax[HW], g_wb[HW], g_wg[HW];
__device__ float g_bhat[HW], g_ghat[HW];

// ===================== PTX helpers (non-'a' features only) =====================
__device__ __forceinline__ uint32_t smem_u32(const void* p) {
    uint32_t a;
    asm("{ .reg .u64 t; cvta.to.shared.u64 t, %1; cvt.u32.u64 %0, t; }" : "=r"(a) : "l"(p));
    return a;
}
__device__ __forceinline__ void cp16(uint32_t saddr, const void* g) {
    asm volatile("cp.async.cg.shared.global [%0], [%1], 16;" :: "r"(saddr), "l"(g));
}
#define CP_COMMIT() asm volatile("cp.async.commit_group;" ::: "memory")
#define CP_WAIT(n)  asm volatile("cp.async.wait_group %0;" :: "n"(n) : "memory")
#define LDSM_X4(r0, r1, r2, r3, addr) \
    asm volatile("ldmatrix.sync.aligned.m8n8.x4.shared.b16 {%0,%1,%2,%3}, [%4];" \
        : "=r"(r0), "=r"(r1), "=r"(r2), "=r"(r3) : "r"(addr))
#define MMA16816(d, a, b) \
    asm volatile("mma.sync.aligned.m16n8k16.row.col.f32.bf16.bf16.f32 " \
        "{%0,%1,%2,%3}, {%4,%5,%6,%7}, {%8,%9}, {%0,%1,%2,%3};" \
        : "+f"((d)[0]), "+f"((d)[1]), "+f"((d)[2]), "+f"((d)[3]) \
        : "r"((a)[0]), "r"((a)[1]), "r"((a)[2]), "r"((a)[3]), "r"((b)[0]), "r"((b)[1]))

// smem tile layout: [128 rows][32 bf16] = 64B rows; 16B-chunk swizzle c ^= (r>>1)&3
__device__ __forceinline__ uint32_t swz(int r, int c) {
    return (uint32_t)(r * 64 + ((c ^ ((r >> 1) & 3)) << 4));
}

// 1a) A': seg0 = hi(full k, padded), seg1 = hi(landmark), seg2 = lo(landmark).
//     flat_src[m*392+k] with s<NF -> 0.01*fs[s] else ls[s-NF].
__global__ void prep_src_bf16(const float* __restrict__ fs, const float* __restrict__ ls) {
    int t = blockIdx.x * blockDim.x + threadIdx.x;
    if (t >= HW * KBIG) return;
    int m = t / KBIG, kp = t - m * KBIG;
    int k;
    bool lo = false;
    if (kp < KSEG)            k = kp;                       // hi, full K
    else if (kp < KSEG + KLM) k = 256 + (kp - KSEG);        // hi, landmark
    else { k = 256 + (kp - KSEG - KLM); lo = true; }        // lo, landmark
    float x = 0.0f;
    if (k < CK) {
        int s = m * CK + k;
        x = (s < NF) ? 0.01f * fs[s] : ls[s - NF];
    }
    __nv_bfloat16 h = __float2bfloat16(x);
    g_Abig[t] = lo ? __float2bfloat16(x - __bfloat162float(h)) : h;
}

// 1b) B' transposed: seg0 = hi(full), seg1 = lo(landmark), seg2 = hi(landmark).
//     REF[k][n] = (k<256 ? 0.01*fr[k*HW+n] : lr[(k-256)*HW+n])
__global__ void prep_ref_bf16(const float* __restrict__ fr, const float* __restrict__ lr) {
    __shared__ float tile[32][33];
    int k0 = blockIdx.y * 32, n0 = blockIdx.x * 32;
    int tx = threadIdx.x, ty = threadIdx.y;   // (32, 8)
#pragma unroll
    for (int i = 0; i < 32; i += 8) {
        int k = k0 + ty + i, n = n0 + tx;
        float x = 0.0f;
        if (k < CK) x = (k < 256) ? 0.01f * fr[k * HW + n] : lr[(k - 256) * HW + n];
        tile[ty + i][tx] = x;
    }
    __syncthreads();
#pragma unroll
    for (int i = 0; i < 32; i += 8) {
        int n = n0 + ty + i, k = k0 + tx;       // k in [0, 416)
        float x = tile[tx][ty + i];
        __nv_bfloat16 h = __float2bfloat16(x);
        size_t o = (size_t)n * KBIG;
        g_Bbig[o + k] = h;                       // seg0: hi full
        if (k >= 256) {                          // landmark (incl. zero pad k>=392)
            int j = k - 256;                     // [0, 160)
            g_Bbig[o + KSEG + j] = __float2bfloat16(x - __bfloat162float(h));  // seg1: lo
            g_Bbig[o + KSEG + KLM + j] = h;                                    // seg2: hi
        }
    }
}

// 2) 1x1 convs (256->1) + mask equality vector.
__global__ void prep_betagama(const float* __restrict__ fr,
                              const int* __restrict__ ms, const int* __restrict__ mr,
                              const float* __restrict__ w1, const float* __restrict__ b1,
                              const float* __restrict__ w2, const float* __restrict__ b2) {
    int p = blockIdx.x * blockDim.x + threadIdx.x;
    if (p >= HW) return;
    float b = b1[0], g = b2[0];
#pragma unroll 8
    for (int c = 0; c < 256; c++) {
        float v = fr[c * HW + p];
        b = fmaf(v, w1[c], b);
        g = fmaf(v, w2[c], g);
    }
    g_beta[p] = b;
    g_gama[p] = g;
    g_M[p] = (ms[p] == mr[p]) ? 1.0f : 0.0f;
}

// 3) bf16 HMMA GEMM: g_A = A'(9216x736) @ B'^T, fp32 accum.
//    128x128 CTA tile, BK=32, 8 warps of 32x64, 3-stage cp.async ring,
//    ONE barrier per K-chunk.
__global__ void __launch_bounds__(256, 2) gemm_hmma_kernel() {
    __shared__ __align__(128) __nv_bfloat16 sA[3][128 * 32];
    __shared__ __align__(128) __nv_bfloat16 sB[3][128 * 32];
    const int tid = threadIdx.x;
    const int wid = tid >> 5, lane = tid & 31;
    const size_t m0 = (size_t)blockIdx.y * 128;
    const size_t n0 = (size_t)blockIdx.x * 128;
    const int mw = (wid & 3) * 32;   // warp m offset in tile
    const int nw = (wid >> 2) * 64;  // warp n offset in tile
    const uint32_t sAu = smem_u32(sA), sBu = smem_u32(sB);

    // per-thread load slots: 16B chunks s = tid and tid+256; r = s/4, c = s%4
    const int lr0 = tid >> 2, lc0 = tid & 3;
    const int lr1 = (tid + 256) >> 2;
    const uint32_t sa0 = swz(lr0, lc0), sa1 = swz(lr1, lc0);
    const __nv_bfloat16* gA0 = g_Abig + (m0 + lr0) * KBIG + lc0 * 8;
    const __nv_bfloat16* gA1 = g_Abig + (m0 + lr1) * KBIG + lc0 * 8;
    const __nv_bfloat16* gB0 = g_Bbig + (n0 + lr0) * KBIG + lc0 * 8;
    const __nv_bfloat16* gB1 = g_Bbig + (n0 + lr1) * KBIG + lc0 * 8;

    float acc[2][8][4];
#pragma unroll
    for (int i = 0; i < 2; i++)
#pragma unroll
        for (int j = 0; j < 8; j++)
#pragma unroll
            for (int q = 0; q < 4; q++) acc[i][j][q] = 0.0f;

    // ldmatrix lane address components (swizzled)
    const int a_r = (lane & 7) + ((lane >> 3) & 1) * 8;
    const int a_c = lane >> 4;
    const int b_r = (lane & 7) + (lane >> 4) * 8;
    const int b_c = (lane >> 3) & 1;

    // prologue: prefetch chunks 0 and 1 into bufs 0 and 1
#pragma unroll
    for (int p = 0; p < 2; ++p) {
        const uint32_t off = (uint32_t)p * 8192;
        const size_t kofs = (size_t)p * 32;
        cp16(sAu + off + sa0, gA0 + kofs); cp16(sAu + off + sa1, gA1 + kofs);
        cp16(sBu + off + sa0, gB0 + kofs); cp16(sBu + off + sa1, gB1 + kofs);
        CP_COMMIT();
    }

    for (int ch = 0; ch < NCHKS; ++ch) {
        if (ch + 1 < NCHKS) { CP_WAIT(1); } else { CP_WAIT(0); }
        __syncthreads();
        if (ch + 2 < NCHKS) {               // refill ring slot (ch+2)%3 (not in flight)
            const uint32_t off = (uint32_t)((ch + 2) % 3) * 8192;
            const size_t kofs = (size_t)(ch + 2) * 32;
            cp16(sAu + off + sa0, gA0 + kofs); cp16(sAu + off + sa1, gA1 + kofs);
            cp16(sBu + off + sa0, gB0 + kofs); cp16(sBu + off + sa1, gB1 + kofs);
            CP_COMMIT();
        }

        const uint32_t ab = sAu + (uint32_t)(ch % 3) * 8192;
        const uint32_t bb = sBu + (uint32_t)(ch % 3) * 8192;
#pragma unroll
        for (int ks = 0; ks < 2; ++ks) {
            uint32_t afr[2][4], bfr[8][2];
#pragma unroll
            for (int mt = 0; mt < 2; ++mt) {
                int r = mw + mt * 16 + a_r;
                LDSM_X4(afr[mt][0], afr[mt][1], afr[mt][2], afr[mt][3],
                        ab + swz(r, 2 * ks + a_c));
            }
#pragma unroll
            for (int np = 0; np < 4; ++np) {
                int r = nw + np * 16 + b_r;
                LDSM_X4(bfr[np * 2][0], bfr[np * 2][1], bfr[np * 2 + 1][0], bfr[np * 2 + 1][1],
                        bb + swz(r, 2 * ks + b_c));
            }
#pragma unroll
            for (int mt = 0; mt < 2; ++mt)
#pragma unroll
                for (int nt = 0; nt < 8; ++nt)
                    MMA16816(acc[mt][nt], afr[mt], bfr[nt]);
        }
    }

    // epilogue: direct stores (lane layout: c0c1 at (m=lane/4, n=2*(lane%4)), c2c3 at m+8)
    const size_t mbase = m0 + mw + (lane >> 2);
    const size_t nbase = n0 + nw + 2 * (lane & 3);
#pragma unroll
    for (int mt = 0; mt < 2; ++mt) {
#pragma unroll
        for (int nt = 0; nt < 8; ++nt) {
            size_t m = mbase + mt * 16;
            size_t n = nbase + nt * 8;
            *(float2*)&g_A[m * HW + n]       = make_float2(acc[mt][nt][0], acc[mt][nt][1]);
            *(float2*)&g_A[(m + 8) * HW + n] = make_float2(acc[mt][nt][2], acc[mt][nt][3]);
        }
    }
}

// 4) Per-column online (max, sum-exp) over a 288-row chunk (coalesced A reads).
__global__ void colstats_kernel() {
    int j = blockIdx.x * blockDim.x + threadIdx.x;
    int i0 = blockIdx.y * ROWS_PER_CHUNK;
    float m = -CUDART_INF_F, s = 0.0f;
    const float* col = g_A + (size_t)i0 * HW + j;
    for (int i = 0; i < ROWS_PER_CHUNK; i++) {
        float v = col[(size_t)i * HW];
        float nm = fmaxf(m, v);
        s = s * __expf(m - nm) + __expf(v - nm);
        m = nm;
    }
    g_pm[blockIdx.y * HW + j] = m;
    g_ps[blockIdx.y * HW + j] = s;
}

// 5) Merge chunk partials; fold mask/beta/gama/colsum into per-column weights.
__global__ void mergestats_kernel() {
    int j = blockIdx.x * blockDim.x + threadIdx.x;
    float m = -CUDART_INF_F;
    for (int c = 0; c < NCHUNK; c++) m = fmaxf(m, g_pm[c * HW + j]);
    float s = 0.0f;
    for (int c = 0; c < NCHUNK; c++) s += g_ps[c * HW + j] * __expf(g_pm[c * HW + j] - m);
    g_colmax[j] = m;
    float inv = g_M[j] / s;
    g_wb[j] = g_beta[j] * inv;
    g_wg[j] = g_gama[j] * inv;
}

// 6) One warp per row: beta_hat[i] = sum_j exp(A[i,j]-colmax[j]) * wb[j], same for gama.
__global__ void rowsum_kernel() {
    int warp = (blockIdx.x * blockDim.x + threadIdx.x) >> 5;
    int lane = threadIdx.x & 31;
    const float* row = g_A + (size_t)warp * HW;
    float b = 0.0f, g = 0.0f;
    for (int j0 = lane * 4; j0 < HW; j0 += 128) {
        float4 v  = *(const float4*)(row + j0);
        float4 cm = *(const float4*)(g_colmax + j0);
        float4 wb = *(const float4*)(g_wb + j0);
        float4 wg = *(const float4*)(g_wg + j0);
        float e;
        e = __expf(v.x - cm.x); b = fmaf(e, wb.x, b); g = fmaf(e, wg.x, g);
        e = __expf(v.y - cm.y); b = fmaf(e, wb.y, b); g = fmaf(e, wg.y, g);
        e = __expf(v.z - cm.z); b = fmaf(e, wb.z, b); g = fmaf(e, wg.z, g);
        e = __expf(v.w - cm.w); b = fmaf(e, wb.w, b); g = fmaf(e, wg.w, g);
    }
#pragma unroll
    for (int o = 16; o > 0; o >>= 1) {
        b += __shfl_down_sync(0xFFFFFFFFu, b, o);
        g += __shfl_down_sync(0xFFFFFFFFu, g, o);
    }
    if (lane == 0) { g_bhat[warp] = b; g_ghat[warp] = g; }
}

// 7) out[c,p] = gama_hat[p]*feat_src[c,p] + beta_hat[p]
__global__ void finalize_kernel(const float* __restrict__ fs, float* __restrict__ out) {
    int t = blockIdx.x * blockDim.x + threadIdx.x;
    if (t >= NF) return;
    int p = t % HW;
    out[t] = fmaf(g_ghat[p], fs[t], g_bhat[p]);
}

extern "C" void kernel_launch(void* const* d_in, const int* in_sizes, int n_in,
                              void* d_out, int out_size) {
    const float* fs = (const float*)d_in[0];
    const float* fr = (const float*)d_in[1];
    const float* ls = (const float*)d_in[2];
    const float* lr = (const float*)d_in[3];
    const int*   ms = (const int*)d_in[4];
    const int*   mr = (const int*)d_in[5];
    const float* w1 = (const float*)d_in[6];
    const float* b1 = (const float*)d_in[7];
    const float* w2 = (const float*)d_in[8];
    const float* b2 = (const float*)d_in[9];
    float* out = (float*)d_out;

    prep_src_bf16<<<(HW * KBIG + 255) / 256, 256>>>(fs, ls);
    dim3 trg(HW / 32, KSEG / 32);              // k covers [0,416) incl. landmark + pads
    prep_ref_bf16<<<trg, dim3(32, 8)>>>(fr, lr);
    prep_betagama<<<(HW + 255) / 256, 256>>>(fr, ms, mr, w1, b1, w2, b2);

    dim3 gemm_grid(HW / 128, HW / 128);        // 72 x 72
    gemm_hmma_kernel<<<gemm_grid, 256>>>();

    dim3 cs_grid(HW / 256, NCHUNK);            // 36 x 32
    colstats_kernel<<<cs_grid, 256>>>();
    mergestats_kernel<<<HW / 256, 256>>>();
    rowsum_kernel<<<(HW * 32) / 256, 256>>>();
    finalize_kernel<<<(NF + 255) / 256, 256>>>(fs, out);
}

// round 12
// speedup vs baseline: 3.1085x; 1.0882x over previous
#include <cuda_runtime.h>
#include <cuda_bf16.h>
#include <math_constants.h>
#include <cstdint>

#define HW 9216            // 96*96
#define CK 392             // 256 + 136
#define NF (256 * HW)
#define KSEG 416           // full-K hi segment (13 chunks of 32)
#define KLM 160            // landmark cross segment (136 padded to 160)
#define KBIG 736           // [Ah_full | Ah_lm | Al_lm] x [Bh_full | Bl_lm | Bh_lm]
#define NCHKS 23           // KBIG / 32
#define NBLK 72            // row blocks of 128 (per-CTA colstat partials)
#define GEMM_DSMEM 65536   // 4-stage ring: 4 x (8KB A + 8KB B)

// ===================== static device scratch =====================
__device__ __align__(16) __nv_bfloat16 g_Abig[(size_t)HW * KBIG]; // (9216,736) K-major
__device__ __align__(16) __nv_bfloat16 g_Bbig[(size_t)HW * KBIG]; // transposed (n,k) K-major
__device__ __align__(16) float g_A[(size_t)HW * HW];              // 340 MB logits
__device__ float g_pm[NBLK * HW];
__device__ float g_ps[NBLK * HW];
__device__ float g_beta[HW], g_gama[HW], g_M[HW];
__device__ float g_colmax[HW], g_wb[HW], g_wg[HW];
__device__ float g_bhat[HW], g_ghat[HW];

// ===================== PTX helpers (non-'a' features only) =====================
__device__ __forceinline__ uint32_t smem_u32(const void* p) {
    uint32_t a;
    asm("{ .reg .u64 t; cvta.to.shared.u64 t, %1; cvt.u32.u64 %0, t; }" : "=r"(a) : "l"(p));
    return a;
}
__device__ __forceinline__ void cp16(uint32_t saddr, const void* g) {
    asm volatile("cp.async.cg.shared.global [%0], [%1], 16;" :: "r"(saddr), "l"(g));
}
#define CP_COMMIT() asm volatile("cp.async.commit_group;" ::: "memory")
#define CP_WAIT(n)  asm volatile("cp.async.wait_group %0;" :: "n"(n) : "memory")
#define LDSM_X4(r0, r1, r2, r3, addr) \
    asm volatile("ldmatrix.sync.aligned.m8n8.x4.shared.b16 {%0,%1,%2,%3}, [%4];" \
        : "=r"(r0), "=r"(r1), "=r"(r2), "=r"(r3) : "r"(addr))
#define MMA16816(d, a, b) \
    asm volatile("mma.sync.aligned.m16n8k16.row.col.f32.bf16.bf16.f32 " \
        "{%0,%1,%2,%3}, {%4,%5,%6,%7}, {%8,%9}, {%0,%1,%2,%3};" \
        : "+f"((d)[0]), "+f"((d)[1]), "+f"((d)[2]), "+f"((d)[3]) \
        : "r"((a)[0]), "r"((a)[1]), "r"((a)[2]), "r"((a)[3]), "r"((b)[0]), "r"((b)[1]))

// smem tile layout: [128 rows][32 bf16] = 64B rows; 16B-chunk swizzle c ^= (r>>1)&3
__device__ __forceinline__ uint32_t swz(int r, int c) {
    return (uint32_t)(r * 64 + ((c ^ ((r >> 1) & 3)) << 4));
}

// 1a) A': seg0 = hi(full k, padded), seg1 = hi(landmark), seg2 = lo(landmark).
__global__ void prep_src_bf16(const float* __restrict__ fs, const float* __restrict__ ls) {
    int t = blockIdx.x * blockDim.x + threadIdx.x;
    if (t >= HW * KBIG) return;
    int m = t / KBIG, kp = t - m * KBIG;
    int k;
    bool lo = false;
    if (kp < KSEG)            k = kp;                       // hi, full K
    else if (kp < KSEG + KLM) k = 256 + (kp - KSEG);        // hi, landmark
    else { k = 256 + (kp - KSEG - KLM); lo = true; }        // lo, landmark
    float x = 0.0f;
    if (k < CK) {
        int s = m * CK + k;
        x = (s < NF) ? 0.01f * fs[s] : ls[s - NF];
    }
    __nv_bfloat16 h = __float2bfloat16(x);
    g_Abig[t] = lo ? __float2bfloat16(x - __bfloat162float(h)) : h;
}

// 1b) B' transposed: seg0 = hi(full), seg1 = lo(landmark), seg2 = hi(landmark).
__global__ void prep_ref_bf16(const float* __restrict__ fr, const float* __restrict__ lr) {
    __shared__ float tile[32][33];
    int k0 = blockIdx.y * 32, n0 = blockIdx.x * 32;
    int tx = threadIdx.x, ty = threadIdx.y;   // (32, 8)
#pragma unroll
    for (int i = 0; i < 32; i += 8) {
        int k = k0 + ty + i, n = n0 + tx;
        float x = 0.0f;
        if (k < CK) x = (k < 256) ? 0.01f * fr[k * HW + n] : lr[(k - 256) * HW + n];
        tile[ty + i][tx] = x;
    }
    __syncthreads();
#pragma unroll
    for (int i = 0; i < 32; i += 8) {
        int n = n0 + ty + i, k = k0 + tx;       // k in [0, 416)
        float x = tile[tx][ty + i];
        __nv_bfloat16 h = __float2bfloat16(x);
        size_t o = (size_t)n * KBIG;
        g_Bbig[o + k] = h;                       // seg0: hi full
        if (k >= 256) {                          // landmark (incl. zero pad k>=392)
            int j = k - 256;                     // [0, 160)
            g_Bbig[o + KSEG + j] = __float2bfloat16(x - __bfloat162float(h));  // seg1: lo
            g_Bbig[o + KSEG + KLM + j] = h;                                    // seg2: hi
        }
    }
}

// 2) 1x1 convs (256->1) + mask equality vector.
__global__ void prep_betagama(const float* __restrict__ fr,
                              const int* __restrict__ ms, const int* __restrict__ mr,
                              const float* __restrict__ w1, const float* __restrict__ b1,
                              const float* __restrict__ w2, const float* __restrict__ b2) {
    int p = blockIdx.x * blockDim.x + threadIdx.x;
    if (p >= HW) return;
    float b = b1[0], g = b2[0];
#pragma unroll 8
    for (int c = 0; c < 256; c++) {
        float v = fr[c * HW + p];
        b = fmaf(v, w1[c], b);
        g = fmaf(v, w2[c], g);
    }
    g_beta[p] = b;
    g_gama[p] = g;
    g_M[p] = (ms[p] == mr[p]) ? 1.0f : 0.0f;
}

// 3) bf16 HMMA GEMM + fused per-CTA column stats.
//    128x128 CTA tile, BK=32, 8 warps of 32x64, 4-stage cp.async ring,
//    one barrier per chunk. Epilogue stores fp32 logits AND per-128-row-block
//    column (max, sum-exp) partials via butterfly shuffles + smem combine.
__global__ void __launch_bounds__(256, 2) gemm_hmma_kernel() {
    extern __shared__ __align__(128) char smem_raw[];
    const uint32_t sAu = smem_u32(smem_raw);            // 4 stages x 8192 B
    const uint32_t sBu = sAu + 32768;                   // 4 stages x 8192 B
    const int tid = threadIdx.x;
    const int wid = tid >> 5, lane = tid & 31;
    const size_t m0 = (size_t)blockIdx.y * 128;
    const size_t n0 = (size_t)blockIdx.x * 128;
    const int mw = (wid & 3) * 32;   // warp m offset in tile
    const int nw = (wid >> 2) * 64;  // warp n offset in tile

    // per-thread load slots: 16B chunks s = tid and tid+256; r = s/4, c = s%4
    const int lr0 = tid >> 2, lc0 = tid & 3;
    const int lr1 = (tid + 256) >> 2;
    const uint32_t sa0 = swz(lr0, lc0), sa1 = swz(lr1, lc0);
    const __nv_bfloat16* gA0 = g_Abig + (m0 + lr0) * KBIG + lc0 * 8;
    const __nv_bfloat16* gA1 = g_Abig + (m0 + lr1) * KBIG + lc0 * 8;
    const __nv_bfloat16* gB0 = g_Bbig + (n0 + lr0) * KBIG + lc0 * 8;
    const __nv_bfloat16* gB1 = g_Bbig + (n0 + lr1) * KBIG + lc0 * 8;

    float acc[2][8][4];
#pragma unroll
    for (int i = 0; i < 2; i++)
#pragma unroll
        for (int j = 0; j < 8; j++)
#pragma unroll
            for (int q = 0; q < 4; q++) acc[i][j][q] = 0.0f;

    // ldmatrix lane address components (swizzled)
    const int a_r = (lane & 7) + ((lane >> 3) & 1) * 8;
    const int a_c = lane >> 4;
    const int b_r = (lane & 7) + (lane >> 4) * 8;
    const int b_c = (lane >> 3) & 1;

    // prologue: prefetch chunks 0..2 into ring slots 0..2
#pragma unroll
    for (int p = 0; p < 3; ++p) {
        const uint32_t off = (uint32_t)p * 8192;
        const size_t kofs = (size_t)p * 32;
        cp16(sAu + off + sa0, gA0 + kofs); cp16(sAu + off + sa1, gA1 + kofs);
        cp16(sBu + off + sa0, gB0 + kofs); cp16(sBu + off + sa1, gB1 + kofs);
        CP_COMMIT();
    }

    for (int ch = 0; ch < NCHKS; ++ch) {
        if (ch < NCHKS - 2)      { CP_WAIT(2); }
        else if (ch == NCHKS - 2){ CP_WAIT(1); }
        else                     { CP_WAIT(0); }
        __syncthreads();
        if (ch + 3 < NCHKS) {    // refill ring slot (ch+3)&3 == (ch-1)&3 (free after barrier)
            const uint32_t off = (uint32_t)((ch + 3) & 3) * 8192;
            const size_t kofs = (size_t)(ch + 3) * 32;
            cp16(sAu + off + sa0, gA0 + kofs); cp16(sAu + off + sa1, gA1 + kofs);
            cp16(sBu + off + sa0, gB0 + kofs); cp16(sBu + off + sa1, gB1 + kofs);
            CP_COMMIT();
        }

        const uint32_t ab = sAu + (uint32_t)(ch & 3) * 8192;
        const uint32_t bb = sBu + (uint32_t)(ch & 3) * 8192;
#pragma unroll
        for (int ks = 0; ks < 2; ++ks) {
            uint32_t afr[2][4], bfr[8][2];
#pragma unroll
            for (int mt = 0; mt < 2; ++mt) {
                int r = mw + mt * 16 + a_r;
                LDSM_X4(afr[mt][0], afr[mt][1], afr[mt][2], afr[mt][3],
                        ab + swz(r, 2 * ks + a_c));
            }
#pragma unroll
            for (int np = 0; np < 4; ++np) {
                int r = nw + np * 16 + b_r;
                LDSM_X4(bfr[np * 2][0], bfr[np * 2][1], bfr[np * 2 + 1][0], bfr[np * 2 + 1][1],
                        bb + swz(r, 2 * ks + b_c));
            }
#pragma unroll
            for (int mt = 0; mt < 2; ++mt)
#pragma unroll
                for (int nt = 0; nt < 8; ++nt)
                    MMA16816(acc[mt][nt], afr[mt], bfr[nt]);
        }
    }

    // ---- store fp32 logits (lane: c0c1 at (m=lane/4, n=2*(lane%4)), c2c3 at m+8) ----
    const size_t mbase = m0 + mw + (lane >> 2);
    const size_t nbase = n0 + nw + 2 * (lane & 3);
#pragma unroll
    for (int mt = 0; mt < 2; ++mt) {
#pragma unroll
        for (int nt = 0; nt < 8; ++nt) {
            size_t m = mbase + mt * 16;
            size_t n = nbase + nt * 8;
            *(float2*)&g_A[m * HW + n]       = make_float2(acc[mt][nt][0], acc[mt][nt][1]);
            *(float2*)&g_A[(m + 8) * HW + n] = make_float2(acc[mt][nt][2], acc[mt][nt][3]);
        }
    }

    // ---- fused per-CTA column stats over this 128-row block ----
    // Column identity within a warp depends only on (nt, lane&3, q&1); xor-shuffles
    // with offsets 4/8/16 reduce over the 8 lane-groups (rows) preserving lane&3.
    __syncthreads();                       // all warps done reading ring; overlay smem
    float* pm_s = (float*)smem_raw;        // [8][64]
    float* ps_s = pm_s + 512;              // [8][64]
#pragma unroll
    for (int nt = 0; nt < 8; ++nt) {
#pragma unroll
        for (int p = 0; p < 2; ++p) {
            float v0 = acc[0][nt][p],     v1 = acc[0][nt][p + 2];
            float v2 = acc[1][nt][p],     v3 = acc[1][nt][p + 2];
            float mx = fmaxf(fmaxf(v0, v1), fmaxf(v2, v3));
#pragma unroll
            for (int o = 4; o < 32; o <<= 1)
                mx = fmaxf(mx, __shfl_xor_sync(0xFFFFFFFFu, mx, o));
            float se = __expf(v0 - mx) + __expf(v1 - mx) + __expf(v2 - mx) + __expf(v3 - mx);
#pragma unroll
            for (int o = 4; o < 32; o <<= 1)
                se += __shfl_xor_sync(0xFFFFFFFFu, se, o);
            if (lane < 4) {
                int cl = nt * 8 + 2 * lane + p;   // column within warp's 64
                pm_s[wid * 64 + cl] = mx;
                ps_s[wid * 64 + cl] = se;
            }
        }
    }
    __syncthreads();
    if (tid < 128) {                       // combine 4 m-warps per n-group
        int g = tid >> 6, c = tid & 63;
        float m = -CUDART_INF_F;
#pragma unroll
        for (int i = 0; i < 4; ++i)
            m = fmaxf(m, pm_s[(g * 4 + i) * 64 + c]);
        float s = 0.0f;
#pragma unroll
        for (int i = 0; i < 4; ++i)
            s += ps_s[(g * 4 + i) * 64 + c] * __expf(pm_s[(g * 4 + i) * 64 + c] - m);
        size_t gc = n0 + g * 64 + c;
        g_pm[blockIdx.y * HW + gc] = m;
        g_ps[blockIdx.y * HW + gc] = s;
    }
}

// 5) Merge per-row-block partials; fold mask/beta/gama/colsum into weights.
__global__ void mergestats_kernel() {
    int j = blockIdx.x * blockDim.x + threadIdx.x;
    float m = -CUDART_INF_F;
    for (int c = 0; c < NBLK; c++) m = fmaxf(m, g_pm[c * HW + j]);
    float s = 0.0f;
    for (int c = 0; c < NBLK; c++) s += g_ps[c * HW + j] * __expf(g_pm[c * HW + j] - m);
    g_colmax[j] = m;
    float inv = g_M[j] / s;
    g_wb[j] = g_beta[j] * inv;
    g_wg[j] = g_gama[j] * inv;
}

// 6) One warp per row: beta_hat[i] = sum_j exp(A[i,j]-colmax[j]) * wb[j], same for gama.
__global__ void rowsum_kernel() {
    int warp = (blockIdx.x * blockDim.x + threadIdx.x) >> 5;
    int lane = threadIdx.x & 31;
    const float* row = g_A + (size_t)warp * HW;
    float b = 0.0f, g = 0.0f;
    for (int j0 = lane * 4; j0 < HW; j0 += 128) {
        float4 v  = *(const float4*)(row + j0);
        float4 cm = *(const float4*)(g_colmax + j0);
        float4 wb = *(const float4*)(g_wb + j0);
        float4 wg = *(const float4*)(g_wg + j0);
        float e;
        e = __expf(v.x - cm.x); b = fmaf(e, wb.x, b); g = fmaf(e, wg.x, g);
        e = __expf(v.y - cm.y); b = fmaf(e, wb.y, b); g = fmaf(e, wg.y, g);
        e = __expf(v.z - cm.z); b = fmaf(e, wb.z, b); g = fmaf(e, wg.z, g);
        e = __expf(v.w - cm.w); b = fmaf(e, wb.w, b); g = fmaf(e, wg.w, g);
    }
#pragma unroll
    for (int o = 16; o > 0; o >>= 1) {
        b += __shfl_down_sync(0xFFFFFFFFu, b, o);
        g += __shfl_down_sync(0xFFFFFFFFu, g, o);
    }
    if (lane == 0) { g_bhat[warp] = b; g_ghat[warp] = g; }
}

// 7) out[c,p] = gama_hat[p]*feat_src[c,p] + beta_hat[p]
__global__ void finalize_kernel(const float* __restrict__ fs, float* __restrict__ out) {
    int t = blockIdx.x * blockDim.x + threadIdx.x;
    if (t >= NF) return;
    int p = t % HW;
    out[t] = fmaf(g_ghat[p], fs[t], g_bhat[p]);
}

extern "C" void kernel_launch(void* const* d_in, const int* in_sizes, int n_in,
                              void* d_out, int out_size) {
    const float* fs = (const float*)d_in[0];
    const float* fr = (const float*)d_in[1];
    const float* ls = (const float*)d_in[2];
    const float* lr = (const float*)d_in[3];
    const int*   ms = (const int*)d_in[4];
    const int*   mr = (const int*)d_in[5];
    const float* w1 = (const float*)d_in[6];
    const float* b1 = (const float*)d_in[7];
    const float* w2 = (const float*)d_in[8];
    const float* b2 = (const float*)d_in[9];
    float* out = (float*)d_out;

    cudaFuncSetAttribute(gemm_hmma_kernel,
                         cudaFuncAttributeMaxDynamicSharedMemorySize, GEMM_DSMEM);

    prep_src_bf16<<<(HW * KBIG + 255) / 256, 256>>>(fs, ls);
    dim3 trg(HW / 32, KSEG / 32);              // k covers [0,416) incl. landmark + pads
    prep_ref_bf16<<<trg, dim3(32, 8)>>>(fr, lr);
    prep_betagama<<<(HW + 255) / 256, 256>>>(fr, ms, mr, w1, b1, w2, b2);

    dim3 gemm_grid(HW / 128, HW / 128);        // 72 x 72
    gemm_hmma_kernel<<<gemm_grid, 256, GEMM_DSMEM>>>();

    mergestats_kernel<<<HW / 256, 256>>>();
    rowsum_kernel<<<(HW * 32) / 256, 256>>>();
    finalize_kernel<<<(NF + 255) / 256, 256>>>(fs, out);
}